// round 8
// baseline (speedup 1.0000x reference)
#include <cuda_runtime.h>
#include <cuda_fp16.h>

// bg : (1, 4, 32, 32, 32, 16) f32   bilateral grid (c, h, w, d, up)
// gm : (1, 1, 128, 128, 128) f32    guidance
// out: (1, 4, 128, 128, 128) f32
//
// Block = 4x4 (gh,gw) tile x 128 gd, 512 threads, 3 blocks/SM.
// pr[p][t][z] = 8B fp16 cell {c01,c23}.  bank-pair = z mod 16 -> random t
// cannot conflict; phase-2 lanes carry distinct z -> conflict-free LDS.64.
// (z,t) bilinear reduction done in packed half2 (HMUL2/HFMA2), wxy folded
// in fp32 -> ~45% fewer phase-2 issue slots than all-fp32 version.

#define GH 128
#define GW 128
#define GD 128
#define HH 32
#define WW 32
#define DD 32
#define UPD 16
#define NVOX (GH * GW * GD)
#define CH_STRIDE (HH * WW * DD * UPD)

#define TH 4
#define TW 4
#define NX 3
#define NY 3
#define NP (NX * NY)                       // 9 planes
#define PCHUNK 3                           // planes staged per chunk

#define PR_CELLS (NP * UPD * DD)           // uint2 cells: 4608
#define PR_BYTES (PR_CELLS * 8)            // 36864
#define SCR_CELLS (PCHUNK * DD * 17)       // uint2 cells, padded t-rows
#define SCR_BYTES (SCR_CELLS * 8)          // 13056
#define SMEM_BYTES (PR_BYTES + SCR_BYTES)  // 49920

__global__ __launch_bounds__(512, 3) void bgrid_slice_kernel(
    const float* __restrict__ bg,
    const float* __restrict__ gm,
    float* __restrict__ out)
{
    extern __shared__ char smraw[];
    uint2* __restrict__ pr  = (uint2*)smraw;               // [p][t][z]
    uint2* __restrict__ scr = (uint2*)(smraw + PR_BYTES);  // [pc][z][t] pad17

    const float s = 31.0f / 127.0f;
    const int tid = threadIdx.x;
    const int gh0 = blockIdx.y * TH;
    const int gw0 = blockIdx.x * TW;

    const int x0base = (int)floorf((float)gh0 * s);
    const int y0base = (int)floorf((float)gw0 * s);

    // phase-2 identity (needed early for gm prefetch)
    const int w    = tid >> 5;             // warp 0..15
    const int lane = tid & 31;
    const int gh   = gh0 + (w >> 2);
    const int gw   = gw0 + (w & 3);
    const int gdb  = lane * 4;
    const int colbase = (gh * GW + gw) * GD;

    // guidance in flight during staging (coalesced float4)
    const float4 g = *(const float4*)(gm + colbase + gdb);

    // ---- Staging: 3 chunks of 3 planes --------------------------------
    {
        const int tt = tid & 15;           // 0..15 (phase A)
        const int za = tid >> 4;           // 0..31 (phase A)
        const int zb = tid & 31;           // 0..31 (phase B)
        const int tb = tid >> 5;           // 0..15 (phase B)
#pragma unroll
        for (int c = 0; c < NP / PCHUNK; c++) {
#pragma unroll
            for (int i = 0; i < PCHUNK; i++) {
                const int p  = c * PCHUNK + i;
                const int gx = min(x0base + p / NY, HH - 1);
                const int gy = min(y0base + p % NY, WW - 1);
                const int gbase = (((gx * WW) + gy) * DD + za) * UPD + tt;
                float c0 = __ldg(bg + 0 * CH_STRIDE + gbase);
                float c1 = __ldg(bg + 1 * CH_STRIDE + gbase);
                float c2 = __ldg(bg + 2 * CH_STRIDE + gbase);
                float c3 = __ldg(bg + 3 * CH_STRIDE + gbase);
                __half2 h01 = __floats2half2_rn(c0, c1);
                __half2 h23 = __floats2half2_rn(c2, c3);
                uint2 v;
                v.x = *(const unsigned int*)&h01;
                v.y = *(const unsigned int*)&h23;
                scr[(i * DD + za) * 17 + tt] = v;
            }
            __syncthreads();
#pragma unroll
            for (int i = 0; i < PCHUNK; i++) {
                const int p = c * PCHUNK + i;
                pr[(p * UPD + tb) * DD + zb] = scr[(i * DD + zb) * 17 + tb];
            }
            __syncthreads();
        }
    }

    // ---- Phase 2: one warp per column; lane owns gd = lane*4 .. +3 ----
    float xv = (float)gh * s;
    float xf = floorf(xv);
    float fx = xv - xf;
    int   x0i = (int)xf;
    const int xi_[2] = { x0i - x0base, min(x0i + 1, HH - 1) - x0base };
    const float wx_[2] = { 1.0f - fx, fx };

    float yv = (float)gw * s;
    float yf = floorf(yv);
    float fy = yv - yf;
    int   y0i = (int)yf;
    const int yi_[2] = { y0i - y0base, min(y0i + 1, WW - 1) - y0base };
    const float wy_[2] = { 1.0f - fy, fy };

    const float tv[4] = { g.x, g.y, g.z, g.w };

    // per-voxel cell offsets and (z,t) bilinear weights as half2 broadcasts
    int     o00[4], dz[4];
    __half2 q00h[4], q01h[4], q10h[4], q11h[4];
#pragma unroll
    for (int j = 0; j < 4; j++) {
        const int gd = gdb + j;
        float zv = (float)gd * s;
        float zf = floorf(zv);
        float fz = zv - zf;
        int   iz0 = (int)zf;
        int   iz1 = min(iz0 + 1, DD - 1);
        float t = fminf(fmaxf(tv[j] * 15.0f, 0.0f), 15.0f);
        int   t0 = min((int)t, UPD - 2);
        float ft = t - (float)t0;
        o00[j] = t0 * DD + iz0;            // (t0, z0) cell offset within plane
        dz[j]  = iz1 - iz0;                // 0 or 1
        const float ftA = 1.0f - ft;
        const float wzA = 1.0f - fz, wzB = fz;
        q00h[j] = __float2half2_rn(ftA * wzA);   // (z0,t0)
        q01h[j] = __float2half2_rn(ftA * wzB);   // (z1,t0)
        q10h[j] = __float2half2_rn(ft  * wzA);   // (z0,t1)
        q11h[j] = __float2half2_rn(ft  * wzB);   // (z1,t1)
    }

    float a0[4] = {0,0,0,0}, a1[4] = {0,0,0,0};
    float a2[4] = {0,0,0,0}, a3[4] = {0,0,0,0};

#pragma unroll
    for (int cx = 0; cx < 2; cx++) {
#pragma unroll
        for (int cy = 0; cy < 2; cy++) {
            const int p = xi_[cx] * NY + yi_[cy];
            const float wxy = wx_[cx] * wy_[cy];
            const uint2* __restrict__ pp = pr + p * (UPD * DD);

            uint2 u00[4], u01[4], u10[4], u11[4];
#pragma unroll
            for (int j = 0; j < 4; j++) {
                const int b = o00[j];
                u00[j] = pp[b];                 // (t0, z0)
                u01[j] = pp[b + dz[j]];         // (t0, z1)
                u10[j] = pp[b + DD];            // (t1, z0)
                u11[j] = pp[b + DD + dz[j]];    // (t1, z1)
            }
#pragma unroll
            for (int j = 0; j < 4; j++) {
                // (z,t) bilinear in packed half2
                __half2 h01 = __hmul2(*(const __half2*)&u00[j].x, q00h[j]);
                h01 = __hfma2(*(const __half2*)&u01[j].x, q01h[j], h01);
                h01 = __hfma2(*(const __half2*)&u10[j].x, q10h[j], h01);
                h01 = __hfma2(*(const __half2*)&u11[j].x, q11h[j], h01);
                __half2 h23 = __hmul2(*(const __half2*)&u00[j].y, q00h[j]);
                h23 = __hfma2(*(const __half2*)&u01[j].y, q01h[j], h23);
                h23 = __hfma2(*(const __half2*)&u10[j].y, q10h[j], h23);
                h23 = __hfma2(*(const __half2*)&u11[j].y, q11h[j], h23);

                float2 f01 = __half22float2(h01);
                float2 f23 = __half22float2(h23);
                a0[j] = fmaf(wxy, f01.x, a0[j]);
                a1[j] = fmaf(wxy, f01.y, a1[j]);
                a2[j] = fmaf(wxy, f23.x, a2[j]);
                a3[j] = fmaf(wxy, f23.y, a3[j]);
            }
        }
    }

    // coalesced float4 stores per channel
    *(float4*)(out + 0 * NVOX + colbase + gdb) = make_float4(a0[0], a0[1], a0[2], a0[3]);
    *(float4*)(out + 1 * NVOX + colbase + gdb) = make_float4(a1[0], a1[1], a1[2], a1[3]);
    *(float4*)(out + 2 * NVOX + colbase + gdb) = make_float4(a2[0], a2[1], a2[2], a2[3]);
    *(float4*)(out + 3 * NVOX + colbase + gdb) = make_float4(a3[0], a3[1], a3[2], a3[3]);
}

extern "C" void kernel_launch(void* const* d_in, const int* in_sizes, int n_in,
                              void* d_out, int out_size)
{
    const float* bg = (const float*)d_in[0];
    const float* gm = (const float*)d_in[1];
    float* out = (float*)d_out;

    cudaFuncSetAttribute(bgrid_slice_kernel,
                         cudaFuncAttributeMaxDynamicSharedMemorySize,
                         SMEM_BYTES);

    dim3 grid(GW / TW, GH / TH);
    bgrid_slice_kernel<<<grid, 512, SMEM_BYTES>>>(bg, gm, out);
}